// round 9
// baseline (speedup 1.0000x reference)
#include <cuda_runtime.h>
#include <cstdint>

// FourierFFTLayer == identity (ifft(fft(x)).real, rel_err ~1.3e-7).
// HBM-bound copy at ~94% of spec. This round isolates store cache policy:
// __ldcs reads (evict-first: read stream barely occupies L2) + DEFAULT
// stores (evict-normal: write burst absorbed by the 126MB L2 as dirty lines,
// deferring DRAM writeback past kernel end and de-interleaving the read and
// write DRAM bursts). Shape unchanged from the measured optimum: x2 MLP,
// 256 threads, 16384 blocks.

__global__ __launch_bounds__(256) void identity_copy_f4x2_wb(
    const float4* __restrict__ in, float4* __restrict__ out, int n4)
{
    int base = blockIdx.x * (blockDim.x * 2) + threadIdx.x;
    const int s = blockDim.x;

    if (base + s < n4) {
        float4 a = __ldcs(in + base);
        float4 b = __ldcs(in + base + s);
        out[base]     = a;   // default (evict-normal) store: lingers dirty in L2
        out[base + s] = b;
    } else {
        #pragma unroll
        for (int k = 0; k < 2; k++) {
            int i = base + k * s;
            if (i < n4) out[i] = __ldcs(in + i);
        }
    }
}

__global__ __launch_bounds__(256) void identity_copy_tail(
    const float* __restrict__ in, float* __restrict__ out, int start, int n)
{
    int i = start + blockIdx.x * blockDim.x + threadIdx.x;
    if (i < n) out[i] = in[i];
}

extern "C" void kernel_launch(void* const* d_in, const int* in_sizes, int n_in,
                              void* d_out, int out_size)
{
    const float* x = (const float*)d_in[0];
    float* out = (float*)d_out;
    int n = in_sizes[0];           // 33,554,432

    int n4 = n / 4;                // 8,388,608 float4
    if (n4 > 0) {
        const int threads = 256;
        const int per_block = threads * 2;             // 512 float4 / block
        int blocks = (n4 + per_block - 1) / per_block; // 16384
        identity_copy_f4x2_wb<<<blocks, threads>>>(
            (const float4*)x, (float4*)out, n4);
    }
    int tail_start = n4 * 4;
    if (n - tail_start > 0) {
        identity_copy_tail<<<1, 256>>>(x, out, tail_start, n);
    }
}

// round 10
// speedup vs baseline: 1.0153x; 1.0153x over previous
#include <cuda_runtime.h>
#include <cstdint>

// FINAL — FourierFFTLayer == identity (ifft(fft(x)).real on real input;
// rel_err ~1.3e-7 << 1e-3 tolerance). Pure HBM-bandwidth-bound copy:
// 256 MB aggregate traffic at ~7.50 TB/s (~94% of 8 TB/s spec), the
// path-independent chip LTS ceiling.
//
// Design space fully measured across 9 rounds:
//   unroll x1/x2/x4/x8 flat grids  -> x2 optimal (35.8us kernel)
//   copy-engine memcpy node        -> worse (45.1us dur)
//   persistent one-wave grid       -> worse (static partition straggler tail)
//   evict-normal stores            -> worse (dirty-L2 writeback contention
//                                     across graph replays)
// Winner: MLP=2 per thread, 256 threads x 16384 blocks (scheduler-side load
// balancing over SM/L2-die speed variance), streaming .cs hints on BOTH
// streams (zero reuse), guard-free fast path on the exact-divide shape.

__global__ __launch_bounds__(256) void identity_copy_f4x2(
    const float4* __restrict__ in, float4* __restrict__ out, int n4)
{
    int base = blockIdx.x * (blockDim.x * 2) + threadIdx.x;
    const int s = blockDim.x;

    if (base + s < n4) {
        float4 a = __ldcs(in + base);
        float4 b = __ldcs(in + base + s);
        __stcs(out + base,     a);
        __stcs(out + base + s, b);
    } else {
        #pragma unroll
        for (int k = 0; k < 2; k++) {
            int i = base + k * s;
            if (i < n4) __stcs(out + i, __ldcs(in + i));
        }
    }
}

__global__ __launch_bounds__(256) void identity_copy_tail(
    const float* __restrict__ in, float* __restrict__ out, int start, int n)
{
    int i = start + blockIdx.x * blockDim.x + threadIdx.x;
    if (i < n) out[i] = in[i];
}

extern "C" void kernel_launch(void* const* d_in, const int* in_sizes, int n_in,
                              void* d_out, int out_size)
{
    const float* x = (const float*)d_in[0];
    float* out = (float*)d_out;
    int n = in_sizes[0];           // 33,554,432

    int n4 = n / 4;                // 8,388,608 float4
    if (n4 > 0) {
        const int threads = 256;
        const int per_block = threads * 2;             // 512 float4 / block
        int blocks = (n4 + per_block - 1) / per_block; // 16384
        identity_copy_f4x2<<<blocks, threads>>>(
            (const float4*)x, (float4*)out, n4);
    }
    int tail_start = n4 * 4;
    if (n - tail_start > 0) {
        identity_copy_tail<<<1, 256>>>(x, out, tail_start, n);
    }
}

// round 11
// speedup vs baseline: 1.0235x; 1.0081x over previous
#include <cuda_runtime.h>
#include <cstdint>

// FourierFFTLayer == identity (ifft(fft(x)).real, rel_err ~1.3e-7 << 1e-3).
// HBM-bound copy at the ~7.5 TB/s path-independent LTS ceiling (94% of spec).
// Final axis sweep: block size. Same winning shape (MLP=2, .cs both streams)
// but 128-thread blocks -> 32768 schedulable units: finer CLC granularity
// halves the tail-wave straggler quantum over per-SM speed variance
// (near/far L2 die 234/262cyc). SM-wide warp count / in-flight bytes
// unchanged (occupancy is warp-limited at 18 regs).

__global__ __launch_bounds__(128) void identity_copy_f4x2_b128(
    const float4* __restrict__ in, float4* __restrict__ out, int n4)
{
    int base = blockIdx.x * (blockDim.x * 2) + threadIdx.x;
    const int s = blockDim.x;

    if (base + s < n4) {
        float4 a = __ldcs(in + base);
        float4 b = __ldcs(in + base + s);
        __stcs(out + base,     a);
        __stcs(out + base + s, b);
    } else {
        #pragma unroll
        for (int k = 0; k < 2; k++) {
            int i = base + k * s;
            if (i < n4) __stcs(out + i, __ldcs(in + i));
        }
    }
}

__global__ __launch_bounds__(256) void identity_copy_tail(
    const float* __restrict__ in, float* __restrict__ out, int start, int n)
{
    int i = start + blockIdx.x * blockDim.x + threadIdx.x;
    if (i < n) out[i] = in[i];
}

extern "C" void kernel_launch(void* const* d_in, const int* in_sizes, int n_in,
                              void* d_out, int out_size)
{
    const float* x = (const float*)d_in[0];
    float* out = (float*)d_out;
    int n = in_sizes[0];           // 33,554,432

    int n4 = n / 4;                // 8,388,608 float4
    if (n4 > 0) {
        const int threads = 128;
        const int per_block = threads * 2;             // 256 float4 / block
        int blocks = (n4 + per_block - 1) / per_block; // 32768
        identity_copy_f4x2_b128<<<blocks, threads>>>(
            (const float4*)x, (float4*)out, n4);
    }
    int tail_start = n4 * 4;
    if (n - tail_start > 0) {
        identity_copy_tail<<<1, 256>>>(x, out, tail_start, n);
    }
}